// round 7
// baseline (speedup 1.0000x reference)
#include <cuda_runtime.h>
#include <math.h>

#define HN 5
#define PP 50
#define BB 2048
#define NEDGEF 5120000.0f
#define EPSBN 1e-5f
#define NBLK 410            // ceil(2048/5)
#define TWO_PI 6.283185307179586f

typedef unsigned long long ull;

// ---- packed f32x2 helpers (SASS FFMA2 path; only reachable via PTX) ----
__device__ __forceinline__ ull pk2(float lo, float hi){ ull r; asm("mov.b64 %0,{%1,%2};":"=l"(r):"f"(lo),"f"(hi)); return r; }
__device__ __forceinline__ void upk2(ull x, float& lo, float& hi){ asm("mov.b64 {%0,%1},%2;":"=f"(lo),"=f"(hi):"l"(x)); }
__device__ __forceinline__ ull fma2(ull a, ull b, ull c){ ull d; asm("fma.rn.f32x2 %0,%1,%2,%3;":"=l"(d):"l"(a),"l"(b),"l"(c)); return d; }
__device__ __forceinline__ ull add2(ull a, ull b){ ull d; asm("add.rn.f32x2 %0,%1,%2;":"=l"(d):"l"(a),"l"(b)); return d; }

// ---- scratch (__device__ globals; no allocations allowed) ----
__device__ float g_acc1[10];   // sum(a1[c]), sum(a1[c]^2)
__device__ float g_acc2[20];   // sum(h1[c]), sum(h1[a]*h1[b]) upper-tri
__device__ float g_F1[25];     // folded layer1: FAfi, Fb1, FAfj, FW13, FW14
__device__ float g_W2f[25];    // BN2-folded W2
__device__ float g_b2f[HN];    // BN2-folded b2

__global__ void k_init() {
    int t = threadIdx.x;
    if (t < 10) g_acc1[t] = 0.0f;
    if (t < 20) g_acc2[t] = 0.0f;
}

// ---------------- stats1: ANALYTIC pass-1 ----------------
// a1(i,j) = sum_k alpha_k(i) * beta_k(j), beta = (1, f_j, u_j, v_j),
// alpha = (b + wf*f_i, A, w3*ar+w4*ai, w3*ai-w4*ar).
// So per-batch sums of a1 and a1^2 are contractions of node second moments.
__global__ __launch_bounds__(256) void k_stats1(
    const float* __restrict__ features, const float* __restrict__ angles,
    const float* __restrict__ W1, const float* __restrict__ b1)
{
    __shared__ float s_blk[10];
    int t = threadIdx.x, w = t >> 5, lane = t & 31;
    if (t < 10) s_blk[t] = 0.0f;
    __syncthreads();
    int batch = blockIdx.x * 8 + w;   // one warp per batch; grid=256 -> 2048 batches

    float Sf=0,Sr=0,Si=0,Su=0,Sv=0,Sff=0,Srr=0,Sii=0,Sfr=0,Sfi=0,Sri=0,Suu=0,Svv=0,Sfu=0,Sfv=0,Suv=0;
    if (batch < BB) {
        for (int k = lane; k < PP; k += 32) {
            int node = batch * PP + k;
            float f = features[node];
            float2 an = ((const float2*)angles)[node];
            float r = an.x, ii = an.y;
            float inv = 1.0f / (r*r + ii*ii);
            float u = r*inv, v = ii*inv;
            Sf += f; Sr += r; Si += ii; Su += u; Sv += v;
            Sff = fmaf(f,f,Sff);  Srr = fmaf(r,r,Srr);   Sii = fmaf(ii,ii,Sii);
            Sfr = fmaf(f,r,Sfr);  Sfi = fmaf(f,ii,Sfi);  Sri = fmaf(r,ii,Sri);
            Suu = fmaf(u,u,Suu);  Svv = fmaf(v,v,Svv);   Sfu = fmaf(f,u,Sfu);
            Sfv = fmaf(f,v,Sfv);  Suv = fmaf(u,v,Suv);
        }
    }
    float m[16] = {Sf,Sr,Si,Su,Sv,Sff,Srr,Sii,Sfr,Sfi,Sri,Suu,Svv,Sfu,Sfv,Suv};
#pragma unroll
    for (int c = 0; c < 16; c++)
#pragma unroll
        for (int o = 16; o > 0; o >>= 1)
            m[c] += __shfl_down_sync(0xffffffffu, m[c], o);

    if (lane == 0 && batch < BB) {
        float SfT=m[0],SrT=m[1],SiT=m[2],SuT=m[3],SvT=m[4],SffT=m[5],SrrT=m[6],SiiT=m[7],
              SfrT=m[8],SfiT=m[9],SriT=m[10],SuuT=m[11],SvvT=m[12],SfuT=m[13],SfvT=m[14],SuvT=m[15];
        const float Pf = (float)PP;
#pragma unroll
        for (int c = 0; c < HN; c++) {
            float w0=__ldg(&W1[c*5+0]), w1=__ldg(&W1[c*5+1]), w2=__ldg(&W1[c*5+2]);
            float w3=__ldg(&W1[c*5+3]), w4=__ldg(&W1[c*5+4]), b=__ldg(&b1[c]);
            float wf = w0 - w2, A = w1 + w2;
            float aS0 = Pf*b + wf*SfT;
            float aS2 = w3*SrT + w4*SiT;
            float aS3 = w3*SiT - w4*SrT;
            float sum1 = aS0*Pf + Pf*A*SfT + aS2*SuT + aS3*SvT;
            float Ma00 = Pf*b*b + 2.0f*b*wf*SfT + wf*wf*SffT;
            float Ma01 = A*aS0;
            float Ma02 = b*aS2 + wf*(w3*SfrT + w4*SfiT);
            float Ma03 = b*aS3 + wf*(w3*SfiT - w4*SfrT);
            float Ma11 = Pf*A*A;
            float Ma12 = A*aS2;
            float Ma13 = A*aS3;
            float Ma22 = w3*w3*SrrT + 2.0f*w3*w4*SriT + w4*w4*SiiT;
            float Ma23 = (w3*w3 - w4*w4)*SriT + w3*w4*(SiiT - SrrT);
            float Ma33 = w3*w3*SiiT - 2.0f*w3*w4*SriT + w4*w4*SrrT;
            float sum2 = Ma00*Pf + Ma11*SffT + Ma22*SuuT + Ma33*SvvT
                 + 2.0f*(Ma01*SfT + Ma02*SuT + Ma03*SvT + Ma12*SfuT + Ma13*SfvT + Ma23*SuvT);
            atomicAdd(&s_blk[c], sum1);
            atomicAdd(&s_blk[HN + c], sum2);
        }
    }
    __syncthreads();
    if (t < 10) atomicAdd(&g_acc1[t], s_blk[t]);
}

// ---------------- finalize 1 (unchanged) ----------------
__global__ void k_fin1(const float* __restrict__ W1, const float* __restrict__ b1,
                       const float* __restrict__ g1, const float* __restrict__ bt1)
{
    int c = threadIdx.x;
    if (c < HN) {
        const float invE = 1.0f / NEDGEF;
        float mean = g_acc1[c] * invE;
        float var  = g_acc1[5 + c] * invE - mean * mean;
        float s1 = g1[c] * rsqrtf(var + EPSBN);
        float o1 = bt1[c] - mean * s1;
        float w0 = W1[c*5+0], w1 = W1[c*5+1], w2 = W1[c*5+2], w3 = W1[c*5+3], w4 = W1[c*5+4];
        g_F1[c]      = s1 * (w0 - w2);
        g_F1[5 + c]  = fmaf(s1, b1[c], o1);
        g_F1[10 + c] = s1 * (w1 + w2);
        g_F1[15 + c] = s1 * w3;
        g_F1[20 + c] = s1 * w4;
    }
}

// ---------------- pass 2: h1 moments, j-split x2, f32x2 packed ----------------
__global__ __launch_bounds__(512, 2) void k_pass2(
    const float* __restrict__ features, const float* __restrict__ angles)
{
    __shared__ float4 s_node[250];
    __shared__ float s_blk[20];
    const int t = threadIdx.x;
    if (t < 20) s_blk[t] = 0.0f;
    if (t < 250) {
        int g2 = t / PP, i2 = t - g2 * PP;
        int b2 = blockIdx.x * 5 + g2;
        if (b2 < BB) {
            int node = b2 * PP + i2;
            float f = features[node];
            float2 an = ((const float2*)angles)[node];
            float inv = 1.0f / (an.x*an.x + an.y*an.y);
            s_node[t] = make_float4(f, an.x*inv, an.y*inv, 0.f);
        }
    }
    __syncthreads();

    const int g = t / 100, rr = t - g * 100, i = rr >> 1, h = rr & 1;
    const int batch = blockIdx.x * 5 + g;
    const bool active = (t < 500) && (batch < BB);

    ull m01=0,m23=0,M0011=0,M2233=0,M0213=0,M0112=0,M2334=0,M0414=0,M2444=0;
    float m4 = 0.f, M03 = 0.f;

    if (active) {
        int node = batch * PP + i;
        float fi = features[node];
        float2 an = ((const float2*)angles)[node];
        float ar = an.x, ai = an.y;
        float th[5], pc[5], qc[5], Af[5];
#pragma unroll
        for (int c = 0; c < 5; c++) {
            float F0=g_F1[c], Fb=g_F1[5+c], F2=g_F1[10+c], F3=g_F1[15+c], F4=g_F1[20+c];
            Af[c] = F2;
            th[c] = fmaf(F0, fi, Fb);
            pc[c] = F3*ar + F4*ai;
            qc[c] = F3*ai - F4*ar;
        }
        ull th01=pk2(th[0],th[1]), th23=pk2(th[2],th[3]);
        ull Af01=pk2(Af[0],Af[1]), Af23=pk2(Af[2],Af[3]);
        ull pc01=pk2(pc[0],pc[1]), pc23=pk2(pc[2],pc[3]);
        ull qc01=pk2(qc[0],qc[1]), qc23=pk2(qc[2],qc[3]);
        float th4=th[4], Af4=Af[4], pc4=pc[4], qc4=qc[4];
        const int base = g * PP + h * 25;
#pragma unroll 5
        for (int j = 0; j < 25; j++) {
            float4 nj = s_node[base + j];
            ull ff = pk2(nj.x,nj.x), uu = pk2(nj.y,nj.y), vv = pk2(nj.z,nj.z);
            ull a01 = fma2(Af01, ff, th01); a01 = fma2(pc01, uu, a01); a01 = fma2(qc01, vv, a01);
            ull a23 = fma2(Af23, ff, th23); a23 = fma2(pc23, uu, a23); a23 = fma2(qc23, vv, a23);
            float a4 = fmaf(Af4, nj.x, th4); a4 = fmaf(pc4, nj.y, a4); a4 = fmaf(qc4, nj.z, a4);
            float h0,h1v,h2v,h3v;
            upk2(a01,h0,h1v); upk2(a23,h2v,h3v);
            h0  = fmaxf(h0,  0.01f*h0);  h1v = fmaxf(h1v, 0.01f*h1v);
            h2v = fmaxf(h2v, 0.01f*h2v); h3v = fmaxf(h3v, 0.01f*h3v);
            float h4 = fmaxf(a4, 0.01f*a4);
            ull h01 = pk2(h0,h1v), h23 = pk2(h2v,h3v);
            ull p12 = pk2(h1v,h2v), p34 = pk2(h3v,h4), p44 = pk2(h4,h4), p24 = pk2(h2v,h4);
            m01 = add2(m01, h01); m23 = add2(m23, h23); m4 += h4;
            M0011 = fma2(h01, h01, M0011);
            M2233 = fma2(h23, h23, M2233);
            M0213 = fma2(h01, h23, M0213);
            M0112 = fma2(h01, p12, M0112);
            M2334 = fma2(h23, p34, M2334);
            M0414 = fma2(h01, p44, M0414);
            M2444 = fma2(p24, p44, M2444);
            M03 = fmaf(h0, h3v, M03);
        }
    }
    // unpack into canonical g_acc2 order: [0..4]=mean, [5..19]=upper-tri (a<=b row-major)
    float v[20];
    upk2(m01, v[0], v[1]); upk2(m23, v[2], v[3]); v[4] = m4;
    upk2(M0011, v[5],  v[10]);
    upk2(M0112, v[6],  v[11]);
    upk2(M0213, v[7],  v[12]);
    v[8] = M03;
    upk2(M0414, v[9],  v[13]);
    upk2(M2233, v[14], v[17]);
    upk2(M2334, v[15], v[18]);
    upk2(M2444, v[16], v[19]);
#pragma unroll
    for (int c = 0; c < 20; c++)
#pragma unroll
        for (int o = 16; o > 0; o >>= 1)
            v[c] += __shfl_down_sync(0xffffffffu, v[c], o);
    if ((t & 31) == 0) {
#pragma unroll
        for (int c = 0; c < 20; c++) atomicAdd(&s_blk[c], v[c]);
    }
    __syncthreads();
    if (t < 20) atomicAdd(&g_acc2[t], s_blk[t]);
}

// ---------------- finalize 2 (unchanged) ----------------
__global__ void k_fin2(const float* __restrict__ W2, const float* __restrict__ b2,
                       const float* __restrict__ g2, const float* __restrict__ bt2)
{
    int c = threadIdx.x;
    if (c < HN) {
        const float invE = 1.0f / NEDGEF;
        float w[HN], m1[HN];
#pragma unroll
        for (int k = 0; k < HN; k++) { w[k] = W2[c*5+k]; m1[k] = g_acc2[k] * invE; }
        float Sm = 0.f;
#pragma unroll
        for (int k = 0; k < HN; k++) Sm = fmaf(w[k], m1[k], Sm);
        float Sq = 0.f;
        int idx = 0;
#pragma unroll
        for (int a = 0; a < HN; a++)
#pragma unroll
            for (int b = a; b < HN; b++) {
                float mm = g_acc2[5 + idx] * invE;
                float term = w[a] * w[b] * mm;
                Sq += (a == b) ? term : 2.0f * term;
                idx++;
            }
        float bc   = b2[c];
        float mean = Sm + bc;
        float ex2  = Sq + bc * (2.0f * Sm + bc);
        float var  = ex2 - mean * mean;
        float s2 = g2[c] * rsqrtf(var + EPSBN);
        float o2 = bt2[c] - mean * s2;
#pragma unroll
        for (int k = 0; k < HN; k++) g_W2f[c*5+k] = s2 * w[k];
        g_b2f[c] = fmaf(s2, bc, o2);
    }
}

// ---------------- pass 3: forward + aggregation, j-split x2, packed ----------------
__global__ __launch_bounds__(512, 2) void k_pass3(
    const float* __restrict__ pt, const float* __restrict__ features,
    const float* __restrict__ angles, const float* __restrict__ W3,
    const float* __restrict__ b3, float* __restrict__ out)
{
    __shared__ float4 s_node[250];
    __shared__ float s_part[250 * 5];
    __shared__ ull sw01[5], sw23[5];
    __shared__ float sw4[5];
    const int t = threadIdx.x;
    if (t < 5) {
        sw01[t] = pk2(g_W2f[t],      g_W2f[5 + t]);
        sw23[t] = pk2(g_W2f[10 + t], g_W2f[15 + t]);
        sw4[t]  = g_W2f[20 + t];
    }
    if (t < 250) {
        int g2 = t / PP, i2 = t - g2 * PP;
        int b2 = blockIdx.x * 5 + g2;
        if (b2 < BB) {
            int node = b2 * PP + i2;
            float f = features[node];
            float2 an = ((const float2*)angles)[node];
            float inv = 1.0f / (an.x*an.x + an.y*an.y);
            s_node[t] = make_float4(f, an.x*inv, an.y*inv, 0.f);
        }
    }
    __syncthreads();

    const int g = t / 100, rr = t - g * 100, i = rr >> 1, h = rr & 1;
    const int batch = blockIdx.x * 5 + g;
    const bool active = (t < 500) && (batch < BB);

    // volatile: keep W2f in shared (LDS broadcast each iter) instead of 30 extra regs
    volatile ull*   w01v = sw01;
    volatile ull*   w23v = sw23;
    volatile float* w4v  = sw4;

    float S0=0,S1=0,S2=0,S3=0,S4=0;
    int node = 0; float ar = 0.f, ai = 0.f;

    if (active) {
        node = batch * PP + i;
        float fi = features[node];
        float2 an = ((const float2*)angles)[node];
        ar = an.x; ai = an.y;
        float th[5], pc[5], qc[5], Af[5];
#pragma unroll
        for (int c = 0; c < 5; c++) {
            float F0=g_F1[c], Fb=g_F1[5+c], F2=g_F1[10+c], F3=g_F1[15+c], F4=g_F1[20+c];
            Af[c] = F2;
            th[c] = fmaf(F0, fi, Fb);
            pc[c] = F3*ar + F4*ai;
            qc[c] = F3*ai - F4*ar;
        }
        ull th01=pk2(th[0],th[1]), th23=pk2(th[2],th[3]);
        ull Af01=pk2(Af[0],Af[1]), Af23=pk2(Af[2],Af[3]);
        ull pc01=pk2(pc[0],pc[1]), pc23=pk2(pc[2],pc[3]);
        ull qc01=pk2(qc[0],qc[1]), qc23=pk2(qc[2],qc[3]);
        float th4=th[4], Af4=Af[4], pc4=pc[4], qc4=qc[4];
        ull rb01 = pk2(g_b2f[0], g_b2f[1]), rb23 = pk2(g_b2f[2], g_b2f[3]);
        float rb4 = g_b2f[4];

        ull S01 = 0, S23 = 0; float S4a = 0.f;
        const int base = g * PP + h * 25;
#pragma unroll 5
        for (int j = 0; j < 25; j++) {
            float4 nj = s_node[base + j];
            ull ff = pk2(nj.x,nj.x), uu = pk2(nj.y,nj.y), vv = pk2(nj.z,nj.z);
            ull a01 = fma2(Af01, ff, th01); a01 = fma2(pc01, uu, a01); a01 = fma2(qc01, vv, a01);
            ull a23 = fma2(Af23, ff, th23); a23 = fma2(pc23, uu, a23); a23 = fma2(qc23, vv, a23);
            float a4 = fmaf(Af4, nj.x, th4); a4 = fmaf(pc4, nj.y, a4); a4 = fmaf(qc4, nj.z, a4);
            float h0,h1v,h2v,h3v;
            upk2(a01,h0,h1v); upk2(a23,h2v,h3v);
            h0  = fmaxf(h0,  0.01f*h0);  h1v = fmaxf(h1v, 0.01f*h1v);
            h2v = fmaxf(h2v, 0.01f*h2v); h3v = fmaxf(h3v, 0.01f*h3v);
            float h4 = fmaxf(a4, 0.01f*a4);

            ull z01 = rb01, z23 = rb23; float z4 = rb4;
            { ull hh=pk2(h0,h0);   ull wa=w01v[0], wb=w23v[0]; z01=fma2(wa,hh,z01); z23=fma2(wb,hh,z23); z4=fmaf(w4v[0],h0,z4); }
            { ull hh=pk2(h1v,h1v); ull wa=w01v[1], wb=w23v[1]; z01=fma2(wa,hh,z01); z23=fma2(wb,hh,z23); z4=fmaf(w4v[1],h1v,z4); }
            { ull hh=pk2(h2v,h2v); ull wa=w01v[2], wb=w23v[2]; z01=fma2(wa,hh,z01); z23=fma2(wb,hh,z23); z4=fmaf(w4v[2],h2v,z4); }
            { ull hh=pk2(h3v,h3v); ull wa=w01v[3], wb=w23v[3]; z01=fma2(wa,hh,z01); z23=fma2(wb,hh,z23); z4=fmaf(w4v[3],h3v,z4); }
            { ull hh=pk2(h4,h4);   ull wa=w01v[4], wb=w23v[4]; z01=fma2(wa,hh,z01); z23=fma2(wb,hh,z23); z4=fmaf(w4v[4],h4,z4); }

            float zz0,zz1,zz2,zz3;
            upk2(z01,zz0,zz1); upk2(z23,zz2,zz3);
            zz0 = fmaxf(zz0, 0.01f*zz0); zz1 = fmaxf(zz1, 0.01f*zz1);
            zz2 = fmaxf(zz2, 0.01f*zz2); zz3 = fmaxf(zz3, 0.01f*zz3);
            z4  = fmaxf(z4,  0.01f*z4);
            S01 = add2(S01, pk2(zz0, zz1));
            S23 = add2(S23, pk2(zz2, zz3));
            S4a += z4;
        }
        upk2(S01, S0, S1); upk2(S23, S2, S3); S4 = S4a;
        if (h == 1) {
            int p = (g * PP + i) * 5;
            s_part[p] = S0; s_part[p+1] = S1; s_part[p+2] = S2; s_part[p+3] = S3; s_part[p+4] = S4;
        }
    }
    __syncthreads();
    if (active && h == 0) {
        int p = (g * PP + i) * 5;
        S0 += s_part[p]; S1 += s_part[p+1]; S2 += s_part[p+2]; S3 += s_part[p+3]; S4 += s_part[p+4];
        const float invP = 1.0f / (float)PP;
        float sn0 = S0*invP, sn1 = S1*invP, sn2 = S2*invP, sn3 = S3*invP, sn4 = S4*invP;
        float mo[5];
#pragma unroll
        for (int kk = 0; kk < 5; kk++) {
            float acc = __ldg(&b3[kk]);
            acc = fmaf(__ldg(&W3[kk*5+0]), sn0, acc);
            acc = fmaf(__ldg(&W3[kk*5+1]), sn1, acc);
            acc = fmaf(__ldg(&W3[kk*5+2]), sn2, acc);
            acc = fmaf(__ldg(&W3[kk*5+3]), sn3, acc);
            acc = fmaf(__ldg(&W3[kk*5+4]), sn4, acc);
            mo[kk] = acc;
        }
        float si, cs;
        sincosf(TWO_PI * mo[4], &si, &cs);
        float* o = out + (size_t)node * 7;
        o[0] = pt[node];
        o[1] = mo[0]; o[2] = mo[1]; o[3] = mo[2]; o[4] = mo[3];
        o[5] = cs * ar - si * ai;
        o[6] = cs * ai + si * ar;
    }
}

extern "C" void kernel_launch(void* const* d_in, const int* in_sizes, int n_in,
                              void* d_out, int out_size)
{
    const float* pt       = (const float*)d_in[0];
    const float* features = (const float*)d_in[1];
    const float* angles   = (const float*)d_in[2];
    const float* W1       = (const float*)d_in[3];
    const float* b1       = (const float*)d_in[4];
    const float* g1       = (const float*)d_in[5];
    const float* bt1      = (const float*)d_in[6];
    const float* W2       = (const float*)d_in[7];
    const float* b2       = (const float*)d_in[8];
    const float* g2       = (const float*)d_in[9];
    const float* bt2      = (const float*)d_in[10];
    const float* W3       = (const float*)d_in[11];
    const float* b3       = (const float*)d_in[12];
    // d_in[13] = edge_index: analytic clique structure, unused.
    float* out = (float*)d_out;

    k_init<<<1, 32>>>();
    k_stats1<<<256, 256>>>(features, angles, W1, b1);   // analytic pass-1
    k_fin1<<<1, 32>>>(W1, b1, g1, bt1);
    k_pass2<<<NBLK, 512>>>(features, angles);
    k_fin2<<<1, 32>>>(W2, b2, g2, bt2);
    k_pass3<<<NBLK, 512>>>(pt, features, angles, W3, b3, out);
}

// round 8
// speedup vs baseline: 1.1001x; 1.1001x over previous
#include <cuda_runtime.h>
#include <math.h>

#define HN 5
#define PP 50
#define BB 2048
#define NEDGEF 5120000.0f
#define EPSBN 1e-5f
#define BPB 2
#define TPB 128
#define NBLK (BB / BPB)        // 1024 blocks
#define TWO_PI 6.283185307179586f

// ---- scratch (__device__ globals; no allocations allowed) ----
__device__ float g_acc1[10];   // sum(a1[c]), sum(a1[c]^2)
__device__ float g_acc2[20];   // sum(h1[c]), sum(h1[a]*h1[b]) upper-tri
__device__ float g_F1[25];     // folded layer1: FAfi, Fb1, FAfj, FW13, FW14
__device__ float g_W2f[25];    // BN2-folded W2
__device__ float g_b2f[HN];    // BN2-folded b2

__global__ void k_init() {
    int t = threadIdx.x;
    if (t < 10) g_acc1[t] = 0.0f;
    if (t < 20) g_acc2[t] = 0.0f;
}

// ---------------- stats1: ANALYTIC pass-1 ----------------
// a1(i,j) = sum_k alpha_k(i) * beta_k(j), beta = (1, f_j, u_j, v_j).
// Per-batch sums of a1 and a1^2 are contractions of per-node second moments.
__global__ __launch_bounds__(256) void k_stats1(
    const float* __restrict__ features, const float* __restrict__ angles,
    const float* __restrict__ W1, const float* __restrict__ b1)
{
    __shared__ float s_blk[10];
    int t = threadIdx.x, w = t >> 5, lane = t & 31;
    if (t < 10) s_blk[t] = 0.0f;
    __syncthreads();
    int batch = blockIdx.x * 8 + w;   // one warp per batch; grid=256 -> 2048 batches

    float Sf=0,Sr=0,Si=0,Su=0,Sv=0,Sff=0,Srr=0,Sii=0,Sfr=0,Sfi=0,Sri=0,Suu=0,Svv=0,Sfu=0,Sfv=0,Suv=0;
    if (batch < BB) {
        for (int k = lane; k < PP; k += 32) {
            int node = batch * PP + k;
            float f = features[node];
            float2 an = ((const float2*)angles)[node];
            float r = an.x, ii = an.y;
            float inv = 1.0f / (r*r + ii*ii);
            float u = r*inv, v = ii*inv;
            Sf += f; Sr += r; Si += ii; Su += u; Sv += v;
            Sff = fmaf(f,f,Sff);  Srr = fmaf(r,r,Srr);   Sii = fmaf(ii,ii,Sii);
            Sfr = fmaf(f,r,Sfr);  Sfi = fmaf(f,ii,Sfi);  Sri = fmaf(r,ii,Sri);
            Suu = fmaf(u,u,Suu);  Svv = fmaf(v,v,Svv);   Sfu = fmaf(f,u,Sfu);
            Sfv = fmaf(f,v,Sfv);  Suv = fmaf(u,v,Suv);
        }
    }
    float m[16] = {Sf,Sr,Si,Su,Sv,Sff,Srr,Sii,Sfr,Sfi,Sri,Suu,Svv,Sfu,Sfv,Suv};
#pragma unroll
    for (int c = 0; c < 16; c++)
#pragma unroll
        for (int o = 16; o > 0; o >>= 1)
            m[c] += __shfl_down_sync(0xffffffffu, m[c], o);

    if (lane == 0 && batch < BB) {
        float SfT=m[0],SrT=m[1],SiT=m[2],SuT=m[3],SvT=m[4],SffT=m[5],SrrT=m[6],SiiT=m[7],
              SfrT=m[8],SfiT=m[9],SriT=m[10],SuuT=m[11],SvvT=m[12],SfuT=m[13],SfvT=m[14],SuvT=m[15];
        const float Pf = (float)PP;
#pragma unroll
        for (int c = 0; c < HN; c++) {
            float w0=__ldg(&W1[c*5+0]), w1=__ldg(&W1[c*5+1]), w2=__ldg(&W1[c*5+2]);
            float w3=__ldg(&W1[c*5+3]), w4=__ldg(&W1[c*5+4]), b=__ldg(&b1[c]);
            float wf = w0 - w2, A = w1 + w2;
            float aS0 = Pf*b + wf*SfT;
            float aS2 = w3*SrT + w4*SiT;
            float aS3 = w3*SiT - w4*SrT;
            float sum1 = aS0*Pf + Pf*A*SfT + aS2*SuT + aS3*SvT;
            float Ma00 = Pf*b*b + 2.0f*b*wf*SfT + wf*wf*SffT;
            float Ma01 = A*aS0;
            float Ma02 = b*aS2 + wf*(w3*SfrT + w4*SfiT);
            float Ma03 = b*aS3 + wf*(w3*SfiT - w4*SfrT);
            float Ma11 = Pf*A*A;
            float Ma12 = A*aS2;
            float Ma13 = A*aS3;
            float Ma22 = w3*w3*SrrT + 2.0f*w3*w4*SriT + w4*w4*SiiT;
            float Ma23 = (w3*w3 - w4*w4)*SriT + w3*w4*(SiiT - SrrT);
            float Ma33 = w3*w3*SiiT - 2.0f*w3*w4*SriT + w4*w4*SrrT;
            float sum2 = Ma00*Pf + Ma11*SffT + Ma22*SuuT + Ma33*SvvT
                 + 2.0f*(Ma01*SfT + Ma02*SuT + Ma03*SvT + Ma12*SfuT + Ma13*SfvT + Ma23*SuvT);
            atomicAdd(&s_blk[c], sum1);
            atomicAdd(&s_blk[HN + c], sum2);
        }
    }
    __syncthreads();
    if (t < 10) atomicAdd(&g_acc1[t], s_blk[t]);
}

// ---------------- finalize 1 ----------------
__global__ void k_fin1(const float* __restrict__ W1, const float* __restrict__ b1,
                       const float* __restrict__ g1, const float* __restrict__ bt1)
{
    int c = threadIdx.x;
    if (c < HN) {
        const float invE = 1.0f / NEDGEF;
        float mean = g_acc1[c] * invE;
        float var  = g_acc1[5 + c] * invE - mean * mean;
        float s1 = g1[c] * rsqrtf(var + EPSBN);
        float o1 = bt1[c] - mean * s1;
        float w0 = W1[c*5+0], w1 = W1[c*5+1], w2 = W1[c*5+2], w3 = W1[c*5+3], w4 = W1[c*5+4];
        g_F1[c]      = s1 * (w0 - w2);        // FAfi
        g_F1[5 + c]  = fmaf(s1, b1[c], o1);   // Fb1
        g_F1[10 + c] = s1 * (w1 + w2);        // FAfj
        g_F1[15 + c] = s1 * w3;               // FW13
        g_F1[20 + c] = s1 * w4;               // FW14
    }
}

// ---------------- pass 2: h1 moments (scalar, small blocks for occupancy) ----------------
__global__ __launch_bounds__(TPB) void k_pass2(
    const float* __restrict__ features, const float* __restrict__ angles)
{
    __shared__ float4 s_node[BPB * PP];
    __shared__ float s_blk[20];
    const int t = threadIdx.x;
    if (t < 20) s_blk[t] = 0.0f;
    const int g = t / PP;
    const int i = t - g * PP;
    const int batch = blockIdx.x * BPB + g;
    const bool active = (t < BPB * PP);
    float fi = 0.f, ar = 0.f, ai = 0.f;
    if (active) {
        int node = batch * PP + i;
        fi = features[node];
        float2 an = ((const float2*)angles)[node];
        ar = an.x; ai = an.y;
        float inv = 1.0f / (ar*ar + ai*ai);
        s_node[t] = make_float4(fi, ar*inv, ai*inv, 0.f);
    }
    __syncthreads();

    float m1a[HN], M2a[15];
#pragma unroll
    for (int c = 0; c < HN; c++) m1a[c] = 0.f;
#pragma unroll
    for (int c = 0; c < 15; c++) M2a[c] = 0.f;

    if (active) {
        float th[HN], Afj[HN], pc[HN], qc[HN];
#pragma unroll
        for (int c = 0; c < HN; c++) {
            float F0 = g_F1[c], Fb = g_F1[5+c], F2 = g_F1[10+c], F3 = g_F1[15+c], F4 = g_F1[20+c];
            Afj[c] = F2;
            th[c]  = fmaf(F0, fi, Fb);
            pc[c]  = F3*ar + F4*ai;
            qc[c]  = F3*ai - F4*ar;
        }
        const int base = g * PP;
#pragma unroll 2
        for (int j = 0; j < PP; j++) {
            float4 nj = s_node[base + j];
            float h1[HN];
#pragma unroll
            for (int c = 0; c < HN; c++) {
                float a = fmaf(Afj[c], nj.x, th[c]);
                a = fmaf(pc[c], nj.y, a);
                a = fmaf(qc[c], nj.z, a);
                h1[c] = fmaxf(a, 0.01f * a);    // leaky relu
                m1a[c] += h1[c];
            }
            int idx = 0;
#pragma unroll
            for (int a2 = 0; a2 < HN; a2++)
#pragma unroll
                for (int b2 = a2; b2 < HN; b2++) {
                    M2a[idx] = fmaf(h1[a2], h1[b2], M2a[idx]);
                    idx++;
                }
        }
    }
#pragma unroll
    for (int c = 0; c < HN; c++)
#pragma unroll
        for (int o = 16; o > 0; o >>= 1)
            m1a[c] += __shfl_down_sync(0xffffffffu, m1a[c], o);
#pragma unroll
    for (int c = 0; c < 15; c++)
#pragma unroll
        for (int o = 16; o > 0; o >>= 1)
            M2a[c] += __shfl_down_sync(0xffffffffu, M2a[c], o);
    if ((t & 31) == 0) {
#pragma unroll
        for (int c = 0; c < HN; c++) atomicAdd(&s_blk[c], m1a[c]);
#pragma unroll
        for (int c = 0; c < 15; c++) atomicAdd(&s_blk[HN + c], M2a[c]);
    }
    __syncthreads();
    if (t < 20) atomicAdd(&g_acc2[t], s_blk[t]);
}

// ---------------- finalize 2 ----------------
__global__ void k_fin2(const float* __restrict__ W2, const float* __restrict__ b2,
                       const float* __restrict__ g2, const float* __restrict__ bt2)
{
    int c = threadIdx.x;
    if (c < HN) {
        const float invE = 1.0f / NEDGEF;
        float w[HN], m1[HN];
#pragma unroll
        for (int k = 0; k < HN; k++) { w[k] = W2[c*5+k]; m1[k] = g_acc2[k] * invE; }
        float Sm = 0.f;
#pragma unroll
        for (int k = 0; k < HN; k++) Sm = fmaf(w[k], m1[k], Sm);
        float Sq = 0.f;
        int idx = 0;
#pragma unroll
        for (int a = 0; a < HN; a++)
#pragma unroll
            for (int b = a; b < HN; b++) {
                float mm = g_acc2[5 + idx] * invE;
                float term = w[a] * w[b] * mm;
                Sq += (a == b) ? term : 2.0f * term;
                idx++;
            }
        float bc   = b2[c];
        float mean = Sm + bc;
        float ex2  = Sq + bc * (2.0f * Sm + bc);
        float var  = ex2 - mean * mean;
        float s2 = g2[c] * rsqrtf(var + EPSBN);
        float o2 = bt2[c] - mean * s2;
#pragma unroll
        for (int k = 0; k < HN; k++) g_W2f[c*5+k] = s2 * w[k];
        g_b2f[c] = fmaf(s2, bc, o2);
    }
}

// ---------------- pass 3: forward + aggregation + output (scalar) ----------------
__global__ __launch_bounds__(TPB) void k_pass3(
    const float* __restrict__ pt, const float* __restrict__ features,
    const float* __restrict__ angles, const float* __restrict__ W3,
    const float* __restrict__ b3, float* __restrict__ out)
{
    __shared__ float4 s_node[BPB * PP];
    const int t = threadIdx.x;
    const int g = t / PP;
    const int i = t - g * PP;
    const int batch = blockIdx.x * BPB + g;
    const bool active = (t < BPB * PP);
    float fi = 0.f, ar = 0.f, ai = 0.f;
    int node = 0;
    if (active) {
        node = batch * PP + i;
        fi = features[node];
        float2 an = ((const float2*)angles)[node];
        ar = an.x; ai = an.y;
        float inv = 1.0f / (ar*ar + ai*ai);
        s_node[t] = make_float4(fi, ar*inv, ai*inv, 0.f);
    }
    __syncthreads();
    if (!active) return;

    float th[HN], Afj[HN], pc[HN], qc[HN];
#pragma unroll
    for (int c = 0; c < HN; c++) {
        float F0 = g_F1[c], Fb = g_F1[5+c], F2 = g_F1[10+c], F3 = g_F1[15+c], F4 = g_F1[20+c];
        Afj[c] = F2;
        th[c]  = fmaf(F0, fi, Fb);
        pc[c]  = F3*ar + F4*ai;
        qc[c]  = F3*ai - F4*ar;
    }
    float W2f[25], b2f[HN];
#pragma unroll
    for (int c = 0; c < 25; c++) W2f[c] = g_W2f[c];
#pragma unroll
    for (int c = 0; c < HN; c++) b2f[c] = g_b2f[c];

    float Sh2[HN];
#pragma unroll
    for (int c = 0; c < HN; c++) Sh2[c] = 0.f;

    const int base = g * PP;
#pragma unroll 2
    for (int j = 0; j < PP; j++) {
        float4 nj = s_node[base + j];
        float h1[HN];
#pragma unroll
        for (int c = 0; c < HN; c++) {
            float a = fmaf(Afj[c], nj.x, th[c]);
            a = fmaf(pc[c], nj.y, a);
            a = fmaf(qc[c], nj.z, a);
            h1[c] = fmaxf(a, 0.01f * a);
        }
#pragma unroll
        for (int c = 0; c < HN; c++) {
            float a2 = b2f[c];
#pragma unroll
            for (int k = 0; k < HN; k++) a2 = fmaf(W2f[c*5+k], h1[k], a2);
            float h2 = fmaxf(a2, 0.01f * a2);
            Sh2[c] += h2;
        }
    }
    // layer 3 applied once to the summed h2 (linear => commutes with mean)
    float sn[HN];
#pragma unroll
    for (int c = 0; c < HN; c++) sn[c] = Sh2[c] * (1.0f / (float)PP);
    float m[HN];
#pragma unroll
    for (int kk = 0; kk < HN; kk++) {
        float acc = __ldg(&b3[kk]);
#pragma unroll
        for (int k = 0; k < HN; k++) acc = fmaf(__ldg(&W3[kk*5+k]), sn[k], acc);
        m[kk] = acc;
    }
    float si, cs;
    sincosf(TWO_PI * m[4], &si, &cs);
    float* o = out + (size_t)node * 7;
    o[0] = pt[node];
    o[1] = m[0];
    o[2] = m[1];
    o[3] = m[2];
    o[4] = m[3];
    o[5] = cs * ar - si * ai;
    o[6] = cs * ai + si * ar;
}

extern "C" void kernel_launch(void* const* d_in, const int* in_sizes, int n_in,
                              void* d_out, int out_size)
{
    const float* pt       = (const float*)d_in[0];
    const float* features = (const float*)d_in[1];
    const float* angles   = (const float*)d_in[2];
    const float* W1       = (const float*)d_in[3];
    const float* b1       = (const float*)d_in[4];
    const float* g1       = (const float*)d_in[5];
    const float* bt1      = (const float*)d_in[6];
    const float* W2       = (const float*)d_in[7];
    const float* b2       = (const float*)d_in[8];
    const float* g2       = (const float*)d_in[9];
    const float* bt2      = (const float*)d_in[10];
    const float* W3       = (const float*)d_in[11];
    const float* b3       = (const float*)d_in[12];
    // d_in[13] = edge_index: analytic clique structure, unused.
    float* out = (float*)d_out;

    k_init<<<1, 32>>>();
    k_stats1<<<256, 256>>>(features, angles, W1, b1);   // analytic pass-1
    k_fin1<<<1, 32>>>(W1, b1, g1, bt1);
    k_pass2<<<NBLK, TPB>>>(features, angles);
    k_fin2<<<1, 32>>>(W2, b2, g2, bt2);
    k_pass3<<<NBLK, TPB>>>(pt, features, angles, W3, b3, out);
}